// round 4
// baseline (speedup 1.0000x reference)
#include <cuda_runtime.h>
#include <cstdint>

#define D_VOCAB 50257
#define D_MODEL 768
#define N_ROWS  4096          // BATCH * POS = 2 * 2048
#define SQRT_DM 27.712812921102035f   // sqrt(768)
#define NTHREADS 256
#define NBLOCKS  16384

// Flat scan: total elements 4096*50257 = 205,852,672 (divisible by 4).
// Each block owns a contiguous, 16B-aligned chunk of the flat one-hot tensor.
// one_hot values are exactly 0.0f / 1.0f, so integer-nonzero checks are exact.
// A uint4 may straddle a row boundary, so each word is tested; a block can find
// up to 2 hits. The finding block performs the gather+scale+bias for its rows.
__global__ void __launch_bounds__(NTHREADS) embed_flat_kernel(
    const uint4* __restrict__ t4, long n4,
    const float* __restrict__ W,
    const float* __restrict__ bias,
    float* __restrict__ out)
{
    const int tid = threadIdx.x;

    __shared__ int  s_cnt;
    __shared__ long s_flat[8];
    if (tid == 0) s_cnt = 0;
    __syncthreads();

    // Contiguous chunk for this block.
    const long chunk = (n4 + NBLOCKS - 1) / NBLOCKS;
    const long start = (long)blockIdx.x * chunk;
    long end = start + chunk;
    if (end > n4) end = n4;

    #pragma unroll 8
    for (long i = start + tid; i < end; i += NTHREADS) {
        uint4 v = __ldcs(t4 + i);                  // streaming: evict-first
        if (v.x | v.y | v.z | v.w) {
            long base = i << 2;
            if (v.x) s_flat[atomicAdd(&s_cnt, 1)] = base;
            if (v.y) s_flat[atomicAdd(&s_cnt, 1)] = base + 1;
            if (v.z) s_flat[atomicAdd(&s_cnt, 1)] = base + 2;
            if (v.w) s_flat[atomicAdd(&s_cnt, 1)] = base + 3;
        }
    }
    __syncthreads();

    // Gather + scale + bias for each hit (expected ~1 per 4 blocks has >=1).
    const int nhits = s_cnt;
    for (int h = 0; h < nhits; h++) {
        const long flat = s_flat[h];
        const int row = (int)(flat / D_VOCAB);
        const int col = (int)(flat - (long)row * D_VOCAB);
        if (tid < D_MODEL / 4) {
            const float4 w = reinterpret_cast<const float4*>(W + (long)col * D_MODEL)[tid];
            const float4 b = reinterpret_cast<const float4*>(bias)[tid];
            float4 o;
            o.x = fmaf(w.x, SQRT_DM, b.x);
            o.y = fmaf(w.y, SQRT_DM, b.y);
            o.z = fmaf(w.z, SQRT_DM, b.z);
            o.w = fmaf(w.w, SQRT_DM, b.w);
            reinterpret_cast<float4*>(out)[(long)row * (D_MODEL / 4) + tid] = o;
        }
    }
}

extern "C" void kernel_launch(void* const* d_in, const int* in_sizes, int n_in,
                              void* d_out, int out_size)
{
    const float* tokens = (const float*)d_in[0];   // [2, 2048, 50257] one-hot fp32
    const float* W      = (const float*)d_in[1];   // [50257, 768]
    const float* bias   = (const float*)d_in[2];   // [768]
    float* out          = (float*)d_out;           // [2, 2048, 768]

    const long n4 = ((long)N_ROWS * D_VOCAB) / 4;  // 51,463,168 uint4

    embed_flat_kernel<<<NBLOCKS, NTHREADS>>>(
        reinterpret_cast<const uint4*>(tokens), n4, W, bias, out);
}

// round 5
// speedup vs baseline: 1.0669x; 1.0669x over previous
#include <cuda_runtime.h>
#include <cstdint>

#define D_VOCAB 50257
#define D_MODEL 768
#define N_ROWS  4096          // BATCH * POS = 2 * 2048
#define SQRT_DM 27.712812921102035f   // sqrt(768)
#define NTHREADS 256

// Four blocks per (batch,pos) row; each scans a quarter of that row's 50257
// one-hot floats. The block whose quarter contains the single nonzero performs
// the gather+scale+bias for the row. one_hot values are exactly 0.0f/1.0f, so
// integer-nonzero checks are exact. All loop indices are int (keeps ptxas
// front-batching the unrolled LDG.128s).
__global__ void __launch_bounds__(NTHREADS) embed_fused_kernel(
    const float* __restrict__ tokens,
    const float* __restrict__ W,
    const float* __restrict__ bias,
    float* __restrict__ out)
{
    const int row = blockIdx.x >> 2;
    const int q   = blockIdx.x & 3;
    const int tid = threadIdx.x;
    const float* rp = tokens + (long)row * D_VOCAB;

    __shared__ int s_col;
    if (tid == 0) s_col = -1;
    __syncthreads();

    // Row start is (row*50257 mod 4) floats past a 16B boundary.
    const int mis = (int)(((uintptr_t)rp >> 2) & 3);
    const int pre = (4 - mis) & 3;                 // scalar prologue count

    const uint4* __restrict__ p4 = reinterpret_cast<const uint4*>(rp + pre);
    const int n4   = (D_VOCAB - pre) >> 2;
    const int tail = (D_VOCAB - pre) & 3;
    const int n4q  = n4 >> 2;

    const int lo = q * n4q;
    const int hi = (q == 3) ? n4 : lo + n4q;

    if (q == 0 && tid < pre && __float_as_uint(rp[tid]) != 0u) s_col = tid;

    #pragma unroll 8
    for (int i = lo + tid; i < hi; i += NTHREADS) {
        uint4 v = __ldcs(p4 + i);                  // streaming: evict-first
        if (v.x | v.y | v.z | v.w) {
            int base = pre + (i << 2);
            if (v.x) s_col = base;
            if (v.y) s_col = base + 1;
            if (v.z) s_col = base + 2;
            if (v.w) s_col = base + 3;
        }
    }

    if (q == 3) {
        const int tstart = pre + (n4 << 2);
        if (tid < tail && __float_as_uint(rp[tstart + tid]) != 0u)
            s_col = tstart + tid;
    }

    __syncthreads();
    const int col = s_col;

    // Only the quarter that found the nonzero emits the output row.
    if (col >= 0 && tid < D_MODEL / 4) {
        const float4 w = reinterpret_cast<const float4*>(W + (long)col * D_MODEL)[tid];
        const float4 b = reinterpret_cast<const float4*>(bias)[tid];
        float4 o;
        o.x = fmaf(w.x, SQRT_DM, b.x);
        o.y = fmaf(w.y, SQRT_DM, b.y);
        o.z = fmaf(w.z, SQRT_DM, b.z);
        o.w = fmaf(w.w, SQRT_DM, b.w);
        reinterpret_cast<float4*>(out)[(long)row * (D_MODEL / 4) + tid] = o;
    }
}

extern "C" void kernel_launch(void* const* d_in, const int* in_sizes, int n_in,
                              void* d_out, int out_size)
{
    const float* tokens = (const float*)d_in[0];   // [2, 2048, 50257] one-hot fp32
    const float* W      = (const float*)d_in[1];   // [50257, 768]
    const float* bias   = (const float*)d_in[2];   // [768]
    float* out          = (float*)d_out;           // [2, 2048, 768]

    embed_fused_kernel<<<4 * N_ROWS, NTHREADS>>>(tokens, W, bias, out);
}